// round 9
// baseline (speedup 1.0000x reference)
#include <cuda_runtime.h>
#include <cuda_fp16.h>
#include <cstdint>

#define N_TOK 32768
#define DIMX  1024
#define HID   2816
#define BK    64                    // halves per k-tile (128B data per row)
#define STAGES 3
#define ROWPITCH 144                // 128B data + 16B pad -> conflict-free ldmatrix
#define A_BYTES (128 * ROWPITCH)    // 18432
#define STAGE_BYTES (2 * A_BYTES)   // A(128 rows) + B(128 rows) = 36864
#define DYN_SMEM (STAGES * STAGE_BYTES)   // 110592
#define NBLK (HID / 64)             // 44 packed w1/w3 blocks per expert

// ---------------- device scratch (no allocations allowed) -------------------
__device__ int    g_count[2];                        // zeroed by detect_kernel
__device__ int    g_slot[N_TOK];                     // token -> slot
__device__ int    g_word_mode = 1;                   // re-armed by rms_scatter
__device__ __half g_xh[(size_t)2 * N_TOK * DIMX];    // gathered x, fp16
__device__ __half g_h [(size_t)2 * N_TOK * HID];     // silu(xW1^T)*(xW3^T), fp16
__device__ float  g_o [(size_t)2 * N_TOK * DIMX];    // h W2^T, fp32
// packed [e][44][128][DIMX]: rows 0-63 = w1 block, rows 64-127 = w3 block
__device__ __half g_w13[(size_t)2 * 2 * HID * DIMX];
__device__ __half g_w2h[(size_t)2 * DIMX * HID];

// ---------------- PTX helpers ------------------------------------------------
__device__ __forceinline__ uint32_t smem_u32(const void* p) {
    uint32_t a;
    asm("{ .reg .u64 t; cvta.to.shared.u64 t, %1; cvt.u32.u64 %0, t; }" : "=r"(a) : "l"(p));
    return a;
}
__device__ __forceinline__ void cp16s(uint32_t dst, const void* src) {
    asm volatile("cp.async.cg.shared.global [%0], [%1], 16;" :: "r"(dst), "l"(src));
}
__device__ __forceinline__ void ldmx4(uint32_t* r, uint32_t addr) {
    asm volatile("ldmatrix.sync.aligned.m8n8.x4.shared.b16 {%0,%1,%2,%3}, [%4];"
                 : "=r"(r[0]), "=r"(r[1]), "=r"(r[2]), "=r"(r[3]) : "r"(addr));
}
__device__ __forceinline__ void mma16816(float* c, const uint32_t* a, const uint32_t* b) {
    asm volatile(
        "mma.sync.aligned.m16n8k16.row.col.f32.f16.f16.f32 "
        "{%0,%1,%2,%3}, {%4,%5,%6,%7}, {%8,%9}, {%0,%1,%2,%3};"
        : "+f"(c[0]), "+f"(c[1]), "+f"(c[2]), "+f"(c[3])
        : "r"(a[0]), "r"(a[1]), "r"(a[2]), "r"(a[3]), "r"(b[0]), "r"(b[1]));
}
__device__ __forceinline__ float silu_f(float x) { return x / (1.0f + __expf(-x)); }

// ---------------- small kernels ----------------------------------------------
// launch 0: detect mask dtype AND zero the routing counters
__global__ void detect_kernel(const unsigned int* __restrict__ m) {
    int i = blockIdx.x * blockDim.x + threadIdx.x;   // 16384 threads = 64KB, in-bounds either way
    if (i == 0) { g_count[0] = 0; g_count[1] = 0; }
    unsigned v = m[i];
    if (v != 0u && v != 1u && v != 0x3F800000u) g_word_mode = 0;
}
// launch 1: route token -> slot and gather+convert its row in one kernel
__global__ void route_gather(const void* __restrict__ masks, const float* __restrict__ x) {
    int t = blockIdx.x;
    __shared__ int s_slot;
    if (threadIdx.x == 0) {
        bool m0;
        if (g_word_mode) m0 = ((const unsigned int*)masks)[t] != 0u;
        else             m0 = ((const unsigned char*)masks)[t] != 0;
        int e = m0 ? 0 : 1;                    // modality 0 wins on overlap
        int s = atomicAdd(&g_count[e], 1);
        int slot = e * N_TOK + s;
        g_slot[t] = slot;
        s_slot = slot;
    }
    __syncthreads();
    int slot = s_slot;
    float4 v = ((const float4*)(x + (size_t)t * DIMX))[threadIdx.x];   // 256 thr * 4
    __half2 h0 = __floats2half2_rn(v.x, v.y);
    __half2 h1 = __floats2half2_rn(v.z, v.w);
    ((uint2*)(g_xh + (size_t)slot * DIMX))[threadIdx.x] =
        make_uint2(*(uint32_t*)&h0, *(uint32_t*)&h1);
}
// launch 2: convert w2 and pack w1/w3 into g_w13 (GEMM1's B-tile layout)
__global__ void cvtw_all(const float4* __restrict__ w1, const float4* __restrict__ w3,
                         const float4* __restrict__ w2,
                         uint2* __restrict__ d13, uint2* __restrict__ d2) {
    const int VPR   = DIMX / 4;                    // 256 float4 per row
    const int vec13 = 2 * 2 * HID * DIMX / 4;      // packed rows = 2*5632
    const int vec2  = 2 * DIMX * HID / 4;
    int stride = gridDim.x * blockDim.x;
    for (int i = blockIdx.x * blockDim.x + threadIdx.x; i < vec13 + vec2; i += stride) {
        float4 v; uint2* d; int di;
        if (i < vec13) {
            int row = i / VPR, k4 = i % VPR;
            int e   = row / (2 * HID);
            int rr  = row % (2 * HID);
            int blk = rr >> 7;                     // 0..43
            int rin = rr & 127;
            const float4* s = (rin < 64) ? w1 : w3;
            int srow = e * HID + blk * 64 + (rin & 63);
            v = s[srow * VPR + k4];
            d = d13; di = i;
        } else {
            int j = i - vec13;
            v = w2[j];
            d = d2; di = j;
        }
        __half2 h0 = __floats2half2_rn(v.x, v.y);
        __half2 h1 = __floats2half2_rn(v.z, v.w);
        d[di] = make_uint2(*(uint32_t*)&h0, *(uint32_t*)&h1);
    }
}

// ---------------- fp16 tensor-core GEMM ---------------------------------------
// BM=128 rows of A per CTA. 8 warps: wr = wid&3 over M (32 rows), wc = wid>>2 over N.
// B tile = 128 contiguous rows of Bsrc (uniform for both variants; w1/w3 pre-packed).
// DUAL : epilogue silu(d1)*d3 -> fp16 C, NTILE=64.  !DUAL: fp32 C, NTILE=128.
// Pipeline: 3 smem stages x BK=64, ONE __syncthreads per k-tile, fragment
// software pipeline: two 8-HMMA half-rounds per kk with LDSMs interleaved.
template <bool DUAL, int K, int NC, int NTILE>
__global__ void __launch_bounds__(256, 2)
gemm_fp16(const __half* __restrict__ A,
          const __half* __restrict__ Bsrc,
          void* __restrict__ Cout)
{
    extern __shared__ char dyn[];
    const int tid = threadIdx.x;
    const int wid = tid >> 5;
    const int l   = tid & 31;
    const int r0  = blockIdx.y * 128;
    const int e   = r0 >> 15;
    if ((r0 & (N_TOK - 1)) >= g_count[e]) return;
    const int cb  = blockIdx.x * NTILE;

    const uint32_t smem = smem_u32(dyn);
    const __half* Bbase = DUAL
        ? Bsrc + ((size_t)(e * NBLK + blockIdx.x) * 128) * K
        : Bsrc + ((size_t)e * NC + cb) * K;

    // ---- strided cp.async descriptors (rows tr, tr+32, tr+64, tr+96) ----
    const int tr = tid >> 3, tc = tid & 7;
    const __half* aSrc = A + (size_t)(r0 + tr) * K + tc * 8;
    const __half* bSrc = Bbase + (size_t)tr * K + tc * 8;
    const uint32_t offA = tr * ROWPITCH + tc * 16;
    const uint32_t offB = A_BYTES + offA;

    // ---- ldmatrix lane offsets ----
    const int wr = wid & 3, wc = wid >> 2;
    const uint32_t a_off0 = (wr * 32 + (l & 15)) * ROWPITCH + (l >> 4) * 16;
    const uint32_t a_off1 = a_off0 + 16 * ROWPITCH;
    constexpr int NW = DUAL ? 32 : 64;
    uint32_t bx_off[2], by_off[2];
#pragma unroll
    for (int ng = 0; ng < 2; ng++) {
        uint32_t base = A_BYTES
            + (wc * NW + ng * 16 + (l & 7) + ((l >> 4) << 3)) * ROWPITCH
            + ((l >> 3) & 1) * 16;
        bx_off[ng] = base;
        by_off[ng] = DUAL ? (base + 64 * ROWPITCH) : (base + 32 * ROWPITCH);
    }

    float acc[2][8][4];
#pragma unroll
    for (int mi = 0; mi < 2; mi++)
#pragma unroll
        for (int ni = 0; ni < 8; ni++)
#pragma unroll
            for (int q = 0; q < 4; q++) acc[mi][ni][q] = 0.f;

    const int KT = K / BK;
    // prologue: fill STAGES-1 stages
#pragma unroll
    for (int s = 0; s < STAGES - 1; s++) {
        const uint32_t sb = smem + s * STAGE_BYTES;
#pragma unroll
        for (int j = 0; j < 4; j++) {
            cp16s(sb + offA + j * 32 * ROWPITCH, aSrc + (size_t)j * 32 * K + s * BK);
            cp16s(sb + offB + j * 32 * ROWPITCH, bSrc + (size_t)j * 32 * K + s * BK);
        }
        asm volatile("cp.async.commit_group;");
    }

    for (int kt = 0; kt < KT; kt++) {
        asm volatile("cp.async.wait_group %0;" :: "n"(STAGES - 2));
        __syncthreads();

        if (kt + STAGES - 1 < KT) {
            const uint32_t dst = smem + ((kt + STAGES - 1) % STAGES) * STAGE_BYTES;
            const int k0 = (kt + STAGES - 1) * BK;
#pragma unroll
            for (int j = 0; j < 4; j++) {
                cp16s(dst + offA + j * 32 * ROWPITCH, aSrc + (size_t)j * 32 * K + k0);
                cp16s(dst + offB + j * 32 * ROWPITCH, bSrc + (size_t)j * 32 * K + k0);
            }
        }
        asm volatile("cp.async.commit_group;");   // uniform group count

        const uint32_t st = smem + (kt % STAGES) * STAGE_BYTES;

        // fragment software pipeline: a double-buffered; bx/by alternate halves
        uint32_t aF[2][2][4], bxF[2][4], byF[2][4];
        ldmx4(aF[0][0], st + a_off0);
        ldmx4(aF[0][1], st + a_off1);
        ldmx4(bxF[0],   st + bx_off[0]);
        ldmx4(bxF[1],   st + bx_off[1]);

#pragma unroll
        for (int kk = 0; kk < 4; kk++) {
            const int cur = kk & 1;
            // by(kk) — latency hidden behind the bx half-round
            ldmx4(byF[0], st + by_off[0] + kk * 32);
            ldmx4(byF[1], st + by_off[1] + kk * 32);
            // half-round 1: ni 0..3 with bx
#pragma unroll
            for (int ni = 0; ni < 4; ni++) {
                const uint32_t* f = &bxF[ni >> 1][(ni & 1) * 2];
                mma16816(acc[0][ni], aF[cur][0], f);
                mma16816(acc[1][ni], aF[cur][1], f);
            }
            // prefetch a(kk+1), bx(kk+1) — hidden behind the by half-round
            if (kk < 3) {
                ldmx4(aF[cur ^ 1][0], st + a_off0 + (kk + 1) * 32);
                ldmx4(aF[cur ^ 1][1], st + a_off1 + (kk + 1) * 32);
                ldmx4(bxF[0], st + bx_off[0] + (kk + 1) * 32);
                ldmx4(bxF[1], st + bx_off[1] + (kk + 1) * 32);
            }
            // half-round 2: ni 4..7 with by
#pragma unroll
            for (int ni = 0; ni < 4; ni++) {
                const uint32_t* f = &byF[ni >> 1][(ni & 1) * 2];
                mma16816(acc[0][ni + 4], aF[cur][0], f);
                mma16816(acc[1][ni + 4], aF[cur][1], f);
            }
        }
    }

    // ---- epilogue ----
    const int tgrp = l >> 2, tq = l & 3;
    if (DUAL) {
        __half* Ch = (__half*)Cout;
#pragma unroll
        for (int mi = 0; mi < 2; mi++) {
            int row0 = r0 + wr * 32 + mi * 16 + tgrp;
#pragma unroll
            for (int ni = 0; ni < 4; ni++) {
                int col = cb + wc * 32 + ni * 8 + 2 * tq;
                float v0 = silu_f(acc[mi][ni][0]) * acc[mi][ni + 4][0];
                float v1 = silu_f(acc[mi][ni][1]) * acc[mi][ni + 4][1];
                float v2 = silu_f(acc[mi][ni][2]) * acc[mi][ni + 4][2];
                float v3 = silu_f(acc[mi][ni][3]) * acc[mi][ni + 4][3];
                __half2 h01 = __floats2half2_rn(v0, v1);
                __half2 h23 = __floats2half2_rn(v2, v3);
                *(__half2*)(Ch + (size_t)row0 * NC + col)       = h01;
                *(__half2*)(Ch + (size_t)(row0 + 8) * NC + col) = h23;
            }
        }
    } else {
        float* Cf = (float*)Cout;
#pragma unroll
        for (int mi = 0; mi < 2; mi++) {
            int row0 = r0 + wr * 32 + mi * 16 + tgrp;
#pragma unroll
            for (int ni = 0; ni < 8; ni++) {
                int col = cb + wc * 64 + ((ni < 4) ? ni * 8 : 32 + (ni - 4) * 8) + 2 * tq;
                *(float2*)(Cf + (size_t)row0 * NC + col) =
                    make_float2(acc[mi][ni][0], acc[mi][ni][1]);
                *(float2*)(Cf + (size_t)(row0 + 8) * NC + col) =
                    make_float2(acc[mi][ni][2], acc[mi][ni][3]);
            }
        }
    }
}

// ---------------- RMSNorm + scale + scatter (also re-arms word_mode) ---------
__global__ void rms_scatter(const float* __restrict__ o,
                            const float* __restrict__ norm_w,
                            float* __restrict__ out)
{
    int t = blockIdx.x;
    int tid = threadIdx.x;
    if (t == 0 && tid == 0) g_word_mode = 1;   // re-arm for next call's detect
    int slot = g_slot[t];
    int e = slot >> 15;

    const float4* orow = (const float4*)(o + (size_t)slot * DIMX);
    float4 v0 = orow[tid], v1 = orow[tid + 128];
    float ss = v0.x*v0.x + v0.y*v0.y + v0.z*v0.z + v0.w*v0.w
             + v1.x*v1.x + v1.y*v1.y + v1.z*v1.z + v1.w*v1.w;
#pragma unroll
    for (int ofs = 16; ofs; ofs >>= 1) ss += __shfl_xor_sync(0xffffffffu, ss, ofs);
    __shared__ float wss[4];
    if ((tid & 31) == 0) wss[tid >> 5] = ss;
    __syncthreads();
    float r = rsqrtf((wss[0] + wss[1] + wss[2] + wss[3]) * (1.0f / DIMX) + 1e-5f);

    const float4* g = (const float4*)(norm_w + (size_t)e * DIMX);
    float4 g0 = g[tid], g1 = g[tid + 128];
    float4* dst = (float4*)(out + (size_t)t * DIMX);
    dst[tid]       = make_float4(v0.x*r*g0.x, v0.y*r*g0.y, v0.z*r*g0.z, v0.w*r*g0.w);
    dst[tid + 128] = make_float4(v1.x*r*g1.x, v1.y*r*g1.y, v1.z*r*g1.z, v1.w*r*g1.w);
}

// ---------------- launcher ----------------------------------------------------
extern "C" void kernel_launch(void* const* d_in, const int* in_sizes, int n_in,
                              void* d_out, int out_size)
{
    const float* x     = (const float*)d_in[0];
    const void*  masks = d_in[1];
    const float* w1    = (const float*)d_in[2];
    const float* w3    = (const float*)d_in[3];
    const float* w2    = (const float*)d_in[4];
    const float* nw    = (const float*)d_in[5];
    float* out = (float*)d_out;

    cudaFuncSetAttribute(gemm_fp16<true,  DIMX, HID,  64>,
                         cudaFuncAttributeMaxDynamicSharedMemorySize, DYN_SMEM);
    cudaFuncSetAttribute(gemm_fp16<false, HID,  DIMX, 128>,
                         cudaFuncAttributeMaxDynamicSharedMemorySize, DYN_SMEM);

    void *xh, *hp, *op, *w13, *w2h;
    cudaGetSymbolAddress(&xh,  g_xh);
    cudaGetSymbolAddress(&hp,  g_h);
    cudaGetSymbolAddress(&op,  g_o);
    cudaGetSymbolAddress(&w13, g_w13);
    cudaGetSymbolAddress(&w2h, g_w2h);

    detect_kernel<<<64, 256>>>((const unsigned int*)masks);            // 0
    route_gather<<<N_TOK, 256>>>(masks, x);                            // 1
    cvtw_all<<<1024, 256>>>((const float4*)w1, (const float4*)w3, (const float4*)w2,
                            (uint2*)w13, (uint2*)w2h);                 // 2

    // GEMM1: [2N,1024] x packed w13 -> fused SwiGLU -> g_h [2N, HID] fp16   // 3
    gemm_fp16<true, DIMX, HID, 64><<<dim3(NBLK, 2 * N_TOK / 128), 256, DYN_SMEM>>>(
        (const __half*)xh, (const __half*)w13, hp);
    // GEMM2: [2N,2816] x w2 -> g_o [2N, DIM] fp32                           // 4
    gemm_fp16<false, HID, DIMX, 128><<<dim3(DIMX / 128, 2 * N_TOK / 128), 256, DYN_SMEM>>>(
        (const __half*)hp, (const __half*)w2h, op);

    rms_scatter<<<N_TOK, 128>>>((const float*)op, nw, out);                  // 5
}

// round 10
// speedup vs baseline: 1.0409x; 1.0409x over previous
#include <cuda_runtime.h>
#include <cuda_fp16.h>
#include <cstdint>

#define N_TOK 32768
#define DIMX  1024
#define HID   2816
#define BK    64                    // halves per k-tile (128B data per row)
#define STAGES 3
#define ROWPITCH 144                // 128B data + 16B pad -> conflict-free ldmatrix
#define A_BYTES (128 * ROWPITCH)    // 18432
#define STAGE_BYTES (2 * A_BYTES)   // A(128 rows) + B(128 rows) = 36864
#define DYN_SMEM (STAGES * STAGE_BYTES)   // 110592

// ---------------- device scratch (no allocations allowed) -------------------
__device__ int    g_count[2];                        // zeroed by detect_kernel
__device__ int    g_slot[N_TOK];                     // token -> slot
__device__ int    g_word_mode = 1;                   // re-armed by rms_scatter
__device__ __half g_xh[(size_t)2 * N_TOK * DIMX];    // gathered x, fp16
__device__ __half g_h [(size_t)2 * N_TOK * HID];     // silu(xW1^T)*(xW3^T), fp16
__device__ __half g_o [(size_t)2 * N_TOK * DIMX];    // h W2^T, fp16
__device__ __half g_w1h[(size_t)2 * HID * DIMX];
__device__ __half g_w3h[(size_t)2 * HID * DIMX];
__device__ __half g_w2h[(size_t)2 * DIMX * HID];

// ---------------- PTX helpers ------------------------------------------------
__device__ __forceinline__ uint32_t smem_u32(const void* p) {
    uint32_t a;
    asm("{ .reg .u64 t; cvta.to.shared.u64 t, %1; cvt.u32.u64 %0, t; }" : "=r"(a) : "l"(p));
    return a;
}
__device__ __forceinline__ void cp16s(uint32_t dst, const void* src) {
    asm volatile("cp.async.cg.shared.global [%0], [%1], 16;" :: "r"(dst), "l"(src));
}
__device__ __forceinline__ void ldmx4(uint32_t* r, uint32_t addr) {
    asm volatile("ldmatrix.sync.aligned.m8n8.x4.shared.b16 {%0,%1,%2,%3}, [%4];"
                 : "=r"(r[0]), "=r"(r[1]), "=r"(r[2]), "=r"(r[3]) : "r"(addr));
}
__device__ __forceinline__ void mma16816(float* c, const uint32_t* a, const uint32_t* b) {
    asm volatile(
        "mma.sync.aligned.m16n8k16.row.col.f32.f16.f16.f32 "
        "{%0,%1,%2,%3}, {%4,%5,%6,%7}, {%8,%9}, {%0,%1,%2,%3};"
        : "+f"(c[0]), "+f"(c[1]), "+f"(c[2]), "+f"(c[3])
        : "r"(a[0]), "r"(a[1]), "r"(a[2]), "r"(a[3]), "r"(b[0]), "r"(b[1]));
}
__device__ __forceinline__ float silu_f(float x) { return x / (1.0f + __expf(-x)); }

// ---------------- small kernels ----------------------------------------------
// launch 0: detect mask dtype AND zero the routing counters
__global__ void detect_kernel(const unsigned int* __restrict__ m) {
    int i = blockIdx.x * blockDim.x + threadIdx.x;   // 16384 threads = 64KB, in-bounds either way
    if (i == 0) { g_count[0] = 0; g_count[1] = 0; }
    unsigned v = m[i];
    if (v != 0u && v != 1u && v != 0x3F800000u) g_word_mode = 0;
}
// launch 1: route token -> slot and gather+convert its row in one kernel
__global__ void route_gather(const void* __restrict__ masks, const float* __restrict__ x) {
    int t = blockIdx.x;
    __shared__ int s_slot;
    if (threadIdx.x == 0) {
        bool m0;
        if (g_word_mode) m0 = ((const unsigned int*)masks)[t] != 0u;
        else             m0 = ((const unsigned char*)masks)[t] != 0;
        int e = m0 ? 0 : 1;                    // modality 0 wins on overlap
        int s = atomicAdd(&g_count[e], 1);
        int slot = e * N_TOK + s;
        g_slot[t] = slot;
        s_slot = slot;
    }
    __syncthreads();
    int slot = s_slot;
    float4 v = ((const float4*)(x + (size_t)t * DIMX))[threadIdx.x];   // 256 thr * 4
    __half2 h0 = __floats2half2_rn(v.x, v.y);
    __half2 h1 = __floats2half2_rn(v.z, v.w);
    ((uint2*)(g_xh + (size_t)slot * DIMX))[threadIdx.x] =
        make_uint2(*(uint32_t*)&h0, *(uint32_t*)&h1);
}
// launch 2: convert all three weight tensors
__global__ void cvtw_all(const float4* __restrict__ w1, const float4* __restrict__ w3,
                         const float4* __restrict__ w2,
                         uint2* __restrict__ d1, uint2* __restrict__ d3,
                         uint2* __restrict__ d2, int n4) {
    int stride = gridDim.x * blockDim.x;
    for (int i = blockIdx.x * blockDim.x + threadIdx.x; i < 3 * n4; i += stride) {
        const float4* s; uint2* d; int j;
        if (i < n4)          { s = w1; d = d1; j = i; }
        else if (i < 2 * n4) { s = w3; d = d3; j = i - n4; }
        else                 { s = w2; d = d2; j = i - 2 * n4; }
        float4 v = s[j];
        __half2 h0 = __floats2half2_rn(v.x, v.y);
        __half2 h1 = __floats2half2_rn(v.z, v.w);
        d[j] = make_uint2(*(uint32_t*)&h0, *(uint32_t*)&h1);
    }
}

// ---------------- fp16 tensor-core GEMM (R8 proven mainloop) ------------------
// BM=128 rows of A per CTA. 8 warps: wr = wid&3 over M (32 rows), wc = wid>>2 over N.
// DUAL : B = [w1 tile (64 rows) | w3 tile (64 rows)]; warp tile 32x32 per side;
//        epilogue silu(d1)*d3 -> fp16 C.   NTILE = 64 (cols per side).
// !DUAL: B = 128-row weight tile; warp tile 32x64; fp16 C.  NTILE = 128.
// Pipeline: 3 stages x BK=64, ONE __syncthreads per k-tile.
template <bool DUAL, int K, int NC, int NTILE>
__global__ void __launch_bounds__(256, 2)
gemm_fp16(const __half* __restrict__ A,
          const __half* __restrict__ W1,
          const __half* __restrict__ W3,
          void* __restrict__ Cout)
{
    extern __shared__ char dyn[];
    const int tid = threadIdx.x;
    const int wid = tid >> 5;
    const int l   = tid & 31;
    const int r0  = blockIdx.y * 128;
    const int e   = r0 >> 15;
    if ((r0 & (N_TOK - 1)) >= g_count[e]) return;
    const int cb  = blockIdx.x * NTILE;

    const uint32_t smem = smem_u32(dyn);
    const __half* W1e = W1 + (size_t)e * NC * K;
    const __half* W3e = DUAL ? (W3 + (size_t)e * NC * K) : W1e;

    // ---- cp.async descriptors: 2048 16B-chunks per stage, 8 per thread ----
    const __half* src[8];
    uint32_t off[8];
#pragma unroll
    for (int i = 0; i < 8; i++) {
        int id = tid + i * 256;
        if (id < 1024) {                      // A: 128 rows x 8 chunks
            int row = id >> 3, c = id & 7;
            src[i] = A + (size_t)(r0 + row) * K + c * 8;
            off[i] = row * ROWPITCH + c * 16;
        } else {                              // B: 128 rows x 8 chunks
            id -= 1024;
            int brow = id >> 3, c = id & 7;
            const __half* p;
            if (DUAL) p = (brow < 64) ? (W1e + (size_t)(cb + brow) * K)
                                      : (W3e + (size_t)(cb + brow - 64) * K);
            else      p = W1e + (size_t)(cb + brow) * K;
            src[i] = p + c * 8;
            off[i] = A_BYTES + brow * ROWPITCH + c * 16;
        }
    }

    // ---- ldmatrix lane offsets (constant across k) ----
    const int wr = wid & 3, wc = wid >> 2;
    constexpr int NW = DUAL ? 32 : 64;        // warp col span per side
    constexpr int NG = DUAL ? 2 : 4;          // ldmatrix.x4 groups per side
    uint32_t a_off[2];
#pragma unroll
    for (int mi = 0; mi < 2; mi++)
        a_off[mi] = (wr * 32 + mi * 16 + (l & 15)) * ROWPITCH + (l >> 4) * 16;
    uint32_t b_off[NG];
#pragma unroll
    for (int ng = 0; ng < NG; ng++)
        b_off[ng] = A_BYTES
                  + (wc * NW + ng * 16 + (l & 7) + ((l >> 4) << 3)) * ROWPITCH
                  + ((l >> 3) & 1) * 16;

    float acc[2][8][4];
#pragma unroll
    for (int mi = 0; mi < 2; mi++)
#pragma unroll
        for (int ni = 0; ni < 8; ni++)
#pragma unroll
            for (int q = 0; q < 4; q++) acc[mi][ni][q] = 0.f;

    const int KT = K / BK;
    // prologue: fill STAGES-1 stages
#pragma unroll
    for (int s = 0; s < STAGES - 1; s++) {
#pragma unroll
        for (int i = 0; i < 8; i++)
            cp16s(smem + s * STAGE_BYTES + off[i], src[i] + s * BK);
        asm volatile("cp.async.commit_group;");
    }

    for (int kt = 0; kt < KT; kt++) {
        asm volatile("cp.async.wait_group %0;" :: "n"(STAGES - 2));
        __syncthreads();

        if (kt + STAGES - 1 < KT) {
            const uint32_t dst = smem + ((kt + STAGES - 1) % STAGES) * STAGE_BYTES;
#pragma unroll
            for (int i = 0; i < 8; i++)
                cp16s(dst + off[i], src[i] + (kt + STAGES - 1) * BK);
        }
        asm volatile("cp.async.commit_group;");   // uniform group count

        const uint32_t st = smem + (kt % STAGES) * STAGE_BYTES;
#pragma unroll
        for (int kk = 0; kk < 4; kk++) {
            uint32_t a[2][4];
#pragma unroll
            for (int mi = 0; mi < 2; mi++) ldmx4(a[mi], st + a_off[mi] + kk * 32);

            if (DUAL) {
                uint32_t b1[2][4], b3[2][4];
#pragma unroll
                for (int ng = 0; ng < 2; ng++) {
                    ldmx4(b1[ng], st + b_off[ng] + kk * 32);
                    ldmx4(b3[ng], st + 64 * ROWPITCH + b_off[ng] + kk * 32);
                }
#pragma unroll
                for (int ni = 0; ni < 4; ni++) {
                    const uint32_t* f1 = &b1[ni >> 1][(ni & 1) * 2];
                    const uint32_t* f3 = &b3[ni >> 1][(ni & 1) * 2];
#pragma unroll
                    for (int mi = 0; mi < 2; mi++) {
                        mma16816(acc[mi][ni],     a[mi], f1);
                        mma16816(acc[mi][ni + 4], a[mi], f3);
                    }
                }
            } else {
                uint32_t b[4][4];
#pragma unroll
                for (int ng = 0; ng < 4; ng++) ldmx4(b[ng], st + b_off[ng] + kk * 32);
#pragma unroll
                for (int ni = 0; ni < 8; ni++) {
                    const uint32_t* f = &b[ni >> 1][(ni & 1) * 2];
#pragma unroll
                    for (int mi = 0; mi < 2; mi++) mma16816(acc[mi][ni], a[mi], f);
                }
            }
        }
    }

    // ---- epilogue (both variants emit fp16) ----
    const int tgrp = l >> 2, tq = l & 3;
    __half* Ch = (__half*)Cout;
    if (DUAL) {
#pragma unroll
        for (int mi = 0; mi < 2; mi++) {
            int row0 = r0 + wr * 32 + mi * 16 + tgrp;
#pragma unroll
            for (int ni = 0; ni < 4; ni++) {
                int col = cb + wc * 32 + ni * 8 + 2 * tq;
                float v0 = silu_f(acc[mi][ni][0]) * acc[mi][ni + 4][0];
                float v1 = silu_f(acc[mi][ni][1]) * acc[mi][ni + 4][1];
                float v2 = silu_f(acc[mi][ni][2]) * acc[mi][ni + 4][2];
                float v3 = silu_f(acc[mi][ni][3]) * acc[mi][ni + 4][3];
                *(__half2*)(Ch + (size_t)row0 * NC + col)       = __floats2half2_rn(v0, v1);
                *(__half2*)(Ch + (size_t)(row0 + 8) * NC + col) = __floats2half2_rn(v2, v3);
            }
        }
    } else {
#pragma unroll
        for (int mi = 0; mi < 2; mi++) {
            int row0 = r0 + wr * 32 + mi * 16 + tgrp;
#pragma unroll
            for (int ni = 0; ni < 8; ni++) {
                int col = cb + wc * 64 + ni * 8 + 2 * tq;
                *(__half2*)(Ch + (size_t)row0 * NC + col) =
                    __floats2half2_rn(acc[mi][ni][0], acc[mi][ni][1]);
                *(__half2*)(Ch + (size_t)(row0 + 8) * NC + col) =
                    __floats2half2_rn(acc[mi][ni][2], acc[mi][ni][3]);
            }
        }
    }
}

// ---------------- RMSNorm + scale + scatter (fp16 in, fp32 out) ---------------
__global__ void rms_scatter(const __half* __restrict__ o,
                            const float* __restrict__ norm_w,
                            float* __restrict__ out)
{
    int t = blockIdx.x;
    int tid = threadIdx.x;
    if (t == 0 && tid == 0) g_word_mode = 1;   // re-arm for next call's detect
    int slot = g_slot[t];
    int e = slot >> 15;

    // 1024 halves per row = 128 uint4; one uint4 (8 halves) per thread
    uint4 d = ((const uint4*)(o + (size_t)slot * DIMX))[tid];
    float2 f0 = __half22float2(*(__half2*)&d.x);
    float2 f1 = __half22float2(*(__half2*)&d.y);
    float2 f2 = __half22float2(*(__half2*)&d.z);
    float2 f3 = __half22float2(*(__half2*)&d.w);
    float ss = f0.x*f0.x + f0.y*f0.y + f1.x*f1.x + f1.y*f1.y
             + f2.x*f2.x + f2.y*f2.y + f3.x*f3.x + f3.y*f3.y;
#pragma unroll
    for (int ofs = 16; ofs; ofs >>= 1) ss += __shfl_xor_sync(0xffffffffu, ss, ofs);
    __shared__ float wss[4];
    if ((tid & 31) == 0) wss[tid >> 5] = ss;
    __syncthreads();
    float r = rsqrtf((wss[0] + wss[1] + wss[2] + wss[3]) * (1.0f / DIMX) + 1e-5f);

    const float4* g = (const float4*)(norm_w + (size_t)e * DIMX);
    float4 g0 = g[2 * tid], g1 = g[2 * tid + 1];
    float4* dst = (float4*)(out + (size_t)t * DIMX);
    dst[2 * tid]     = make_float4(f0.x*r*g0.x, f0.y*r*g0.y, f1.x*r*g0.z, f1.y*r*g0.w);
    dst[2 * tid + 1] = make_float4(f2.x*r*g1.x, f2.y*r*g1.y, f3.x*r*g1.z, f3.y*r*g1.w);
}

// ---------------- launcher ----------------------------------------------------
extern "C" void kernel_launch(void* const* d_in, const int* in_sizes, int n_in,
                              void* d_out, int out_size)
{
    const float* x     = (const float*)d_in[0];
    const void*  masks = d_in[1];
    const float* w1    = (const float*)d_in[2];
    const float* w3    = (const float*)d_in[3];
    const float* w2    = (const float*)d_in[4];
    const float* nw    = (const float*)d_in[5];
    float* out = (float*)d_out;

    cudaFuncSetAttribute(gemm_fp16<true,  DIMX, HID,  64>,
                         cudaFuncAttributeMaxDynamicSharedMemorySize, DYN_SMEM);
    cudaFuncSetAttribute(gemm_fp16<false, HID,  DIMX, 128>,
                         cudaFuncAttributeMaxDynamicSharedMemorySize, DYN_SMEM);

    void *xh, *hp, *op, *w1h, *w3h, *w2h;
    cudaGetSymbolAddress(&xh,  g_xh);
    cudaGetSymbolAddress(&hp,  g_h);
    cudaGetSymbolAddress(&op,  g_o);
    cudaGetSymbolAddress(&w1h, g_w1h);
    cudaGetSymbolAddress(&w3h, g_w3h);
    cudaGetSymbolAddress(&w2h, g_w2h);

    detect_kernel<<<64, 256>>>((const unsigned int*)masks);            // 0
    route_gather<<<N_TOK, 256>>>(masks, x);                            // 1

    const int n4 = 2 * HID * DIMX / 4;
    cvtw_all<<<1024, 256>>>((const float4*)w1, (const float4*)w3, (const float4*)w2,
                            (uint2*)w1h, (uint2*)w3h, (uint2*)w2h, n4);        // 2

    // GEMM1: [2N,1024] x w1/w3 -> fused SwiGLU -> g_h [2N, HID] fp16          // 3
    gemm_fp16<true, DIMX, HID, 64><<<dim3(HID / 64, 2 * N_TOK / 128), 256, DYN_SMEM>>>(
        (const __half*)xh, (const __half*)w1h, (const __half*)w3h, hp);
    // GEMM2: [2N,2816] x w2 -> g_o [2N, DIM] fp16                             // 4
    gemm_fp16<false, HID, DIMX, 128><<<dim3(DIMX / 128, 2 * N_TOK / 128), 256, DYN_SMEM>>>(
        (const __half*)hp, (const __half*)w2h, (const __half*)w2h, op);

    rms_scatter<<<N_TOK, 128>>>((const __half*)op, nw, out);                   // 5
}